// round 10
// baseline (speedup 1.0000x reference)
#include <cuda_runtime.h>
#include <cuda_fp16.h>
#include <math.h>

#define NN 50000
#define EE 800000
#define FIN 128
#define HH 256
#define CC 112
#define LL 8
#define EPSBN 1e-5f
#define NB_SCAN 196   // ceil(NN/256)

typedef unsigned long long u64;

__device__ __forceinline__ u64 pack2(float lo, float hi) {
    u64 d; asm("mov.b64 %0, {%1, %2};" : "=l"(d) : "f"(lo), "f"(hi)); return d;
}
__device__ __forceinline__ void fma2(u64& d, u64 a, u64 b, u64 c) {
    asm("fma.rn.f32x2 %0, %1, %2, %3;" : "=l"(d) : "l"(a), "l"(b), "l"(c));
}
__device__ __forceinline__ float2 unpack2(u64 v) {
    float2 r; asm("mov.b64 {%0, %1}, %2;" : "=f"(r.x), "=f"(r.y) : "l"(v)); return r;
}
__device__ __forceinline__ float2 h2f(unsigned int u) {
    __half2 h = *reinterpret_cast<__half2*>(&u);
    return __half22float2(h);
}

// ---------------- scratch (device globals; no allocation allowed) ------------
__device__ __align__(16) float  g_h[NN * HH];
__device__ __align__(16) __half g_t[NN * HH];
__device__ __align__(16) float  g_acc[NN * HH];
__device__ __align__(16) int    g_deg1[NN];
__device__ __align__(16) int    g_deg2[NN];
__device__ __align__(16) int    g_row1[NN + 4];
__device__ __align__(16) int    g_row2[NN + 4];
__device__ __align__(16) int    g_cur1[NN];
__device__ __align__(16) int    g_cur2[NN];
__device__ __align__(16) int    g_src1[EE];
__device__ __align__(16) int    g_src2[EE];
__device__ __align__(16) float  g_nrm1[EE];
__device__ __align__(16) float  g_nrm2[EE];
__device__ __align__(16) float  g_dinv1[NN];
__device__ __align__(16) float  g_dinv2[NN];
__device__ __align__(16) float  g_self1[NN];
__device__ __align__(16) float  g_self2[NN];
__device__ __align__(16) int    g_part[256];
__device__ __align__(16) float  g_stats[2 * HH];   // sum, sumsq
__device__ __align__(16) float  g_ab[2 * HH];      // scale a, shift b
__device__ __align__(16) float  g_w[LL];

// ---------------- utility kernels -------------------------------------------
__global__ void zero_kernel(float4* p, int n4) {
    int i = blockIdx.x * blockDim.x + threadIdx.x;
    if (i < n4) p[i] = make_float4(0.f, 0.f, 0.f, 0.f);
}

__global__ void deg_kernel(const int* __restrict__ e1, const int* __restrict__ e2) {
    int i = blockIdx.x * blockDim.x + threadIdx.x;
    if (i < EE) {
        atomicAdd(&g_deg1[e1[EE + i]], 1);
        atomicAdd(&g_deg2[e2[EE + i]], 1);
    }
}

__global__ void dinv_kernel() {
    int i = blockIdx.x * blockDim.x + threadIdx.x;
    if (i < NN) {
        float d1 = rsqrtf((float)g_deg1[i] + 1.0f);   // +1 = self loop
        float d2 = rsqrtf((float)g_deg2[i] + 1.0f);
        g_dinv1[i] = d1;
        g_dinv2[i] = d2;
        g_self1[i] = d1 * d1;
        g_self2[i] = d2 * d2;
    }
}

__global__ void scan1_kernel(const int* __restrict__ deg, int* __restrict__ row,
                             int* __restrict__ partial) {
    __shared__ int s[256];
    int tid = threadIdx.x;
    int i = blockIdx.x * 256 + tid;
    int v = (i < NN) ? deg[i] : 0;
    s[tid] = v;
    __syncthreads();
#pragma unroll
    for (int off = 1; off < 256; off <<= 1) {
        int t = (tid >= off) ? s[tid - off] : 0;
        __syncthreads();
        s[tid] += t;
        __syncthreads();
    }
    if (i < NN) row[i] = s[tid] - v;   // exclusive
    if (tid == 255) partial[blockIdx.x] = s[255];
}

__global__ void scan2_kernel(int* __restrict__ partial) {
    __shared__ int s[256];
    int tid = threadIdx.x;
    int v = (tid < NB_SCAN) ? partial[tid] : 0;
    s[tid] = v;
    __syncthreads();
#pragma unroll
    for (int off = 1; off < 256; off <<= 1) {
        int t = (tid >= off) ? s[tid - off] : 0;
        __syncthreads();
        s[tid] += t;
        __syncthreads();
    }
    if (tid < NB_SCAN) partial[tid] = s[tid] - v;
}

__global__ void scan3_kernel(int* __restrict__ row, const int* __restrict__ partial,
                             int* __restrict__ cur) {
    int i = blockIdx.x * blockDim.x + threadIdx.x;
    if (i < NN) {
        int r = row[i] + partial[i >> 8];
        row[i] = r;
        cur[i] = r;
    }
    if (i == 0) row[NN] = EE;
}

__global__ void fill_kernel(const int* __restrict__ e1, const int* __restrict__ e2) {
    int i = blockIdx.x * blockDim.x + threadIdx.x;
    if (i < EE) {
        int s1 = e1[i], c1 = e1[EE + i];
        int p = atomicAdd(&g_cur1[c1], 1);
        g_src1[p] = s1;
        g_nrm1[p] = g_dinv1[s1] * g_dinv1[c1];
        int s2 = e2[i], c2 = e2[EE + i];
        p = atomicAdd(&g_cur2[c2], 1);
        g_src2[p] = s2;
        g_nrm2[p] = g_dinv2[s2] * g_dinv2[c2];
    }
}

__global__ void softmax_w_kernel(const float* __restrict__ lw) {
    if (threadIdx.x == 0 && blockIdx.x == 0) {
        float m = lw[0];
        for (int i = 1; i < LL; i++) m = fmaxf(m, lw[i]);
        float e[LL];
        float s = 0.f;
        for (int i = 0; i < LL; i++) { e[i] = expf(lw[i] - m); s += e[i]; }
        float inv = 1.0f / s;
        for (int i = 0; i < LL; i++) g_w[i] = e[i] * inv;
    }
}

// ---------------- SGEMM: C = act(A) @ B + bias -------------------------------
// Double-buffered smem with register prefetch. Packed f32x2 FMA inner loop.
// act(v,k) = relu(ab[k]*v + ab[HH+k]) when ab != nullptr (fused BN+ReLU).
// When wPtr != nullptr and blockIdx.x == 0: accOut[r,k] += wPtr[widx]*act(A[r,k]).
// HALF_OUT: write C as __half (for t consumed by SpMM), else float.
template <bool HALF_OUT>
__global__ __launch_bounds__(256) void sgemm_kernel(
    const float* __restrict__ A, const float* __restrict__ B,
    const float* __restrict__ bias, void* __restrict__ Cout,
    int M, int Ncols, int K, const float* __restrict__ ab,
    const float* __restrict__ wPtr, int widx, float* __restrict__ accOut)
{
    __shared__ float As[2][16][128];
    __shared__ float Bs[2][16][128];
    const int tid = threadIdx.x;
    const int tx = tid & 15;
    const int ty = tid >> 4;
    const int rowBase = blockIdx.y * 128;
    const int colBase = blockIdx.x * 128;
    const int aRow = tid >> 2;          // 0..63
    const int aCol = (tid & 3) * 4;     // 0,4,8,12
    const int bRow = tid >> 5;          // 0..7
    const int bCol = (tid & 31) * 4;    // 0..124

    const bool doAct = (ab != nullptr);
    const bool doAcc = (wPtr != nullptr) && (blockIdx.x == 0);
    const float wres = doAcc ? wPtr[widx] : 0.f;
    const int grA0 = rowBase + aRow;
    const int grA1 = grA0 + 64;
    const int nt = K >> 4;

    u64 acc2[8][4];
#pragma unroll
    for (int i = 0; i < 8; i++)
#pragma unroll
        for (int j = 0; j < 4; j++) acc2[i][j] = 0ull;

    float4 aR0, aR1, bR0, bR1, avR, bvR;

    // ---- prefetch tile 0 ----
    {
        const int k0 = 0;
        avR = doAct ? *(const float4*)(ab + k0 + aCol) : make_float4(1.f, 1.f, 1.f, 1.f);
        bvR = doAct ? *(const float4*)(ab + HH + k0 + aCol) : make_float4(0.f, 0.f, 0.f, 0.f);
        aR0 = (grA0 < M) ? *(const float4*)(A + (long)grA0 * K + k0 + aCol)
                         : make_float4(0.f, 0.f, 0.f, 0.f);
        aR1 = (grA1 < M) ? *(const float4*)(A + (long)grA1 * K + k0 + aCol)
                         : make_float4(0.f, 0.f, 0.f, 0.f);
        bR0 = *(const float4*)(B + (long)(k0 + bRow) * Ncols + colBase + bCol);
        bR1 = *(const float4*)(B + (long)(k0 + bRow + 8) * Ncols + colBase + bCol);
    }
    // ---- store tile 0 into buffer 0 ----
    {
        const int k0 = 0;
#pragma unroll
        for (int s = 0; s < 2; s++) {
            float4 v = s ? aR1 : aR0;
            int gr = s ? grA1 : grA0;
            int r = aRow + s * 64;
            if (doAct && gr < M) {
                v.x = fmaxf(fmaf(v.x, avR.x, bvR.x), 0.f);
                v.y = fmaxf(fmaf(v.y, avR.y, bvR.y), 0.f);
                v.z = fmaxf(fmaf(v.z, avR.z, bvR.z), 0.f);
                v.w = fmaxf(fmaf(v.w, avR.w, bvR.w), 0.f);
            }
            if (doAcc && gr < M) {
                float* ap = accOut + (long)gr * K + k0 + aCol;
                float4 ac = *(const float4*)ap;
                ac.x = fmaf(wres, v.x, ac.x);
                ac.y = fmaf(wres, v.y, ac.y);
                ac.z = fmaf(wres, v.z, ac.z);
                ac.w = fmaf(wres, v.w, ac.w);
                *(float4*)ap = ac;
            }
            As[0][aCol + 0][r] = v.x;
            As[0][aCol + 1][r] = v.y;
            As[0][aCol + 2][r] = v.z;
            As[0][aCol + 3][r] = v.w;
        }
        *(float4*)(&Bs[0][bRow][bCol]) = bR0;
        *(float4*)(&Bs[0][bRow + 8][bCol]) = bR1;
    }
    __syncthreads();

    int p = 0;
    for (int kt = 0; kt < nt; kt++) {
        const bool more = (kt + 1 < nt);
        if (more) {
            const int k0 = (kt + 1) << 4;
            avR = doAct ? *(const float4*)(ab + k0 + aCol) : make_float4(1.f, 1.f, 1.f, 1.f);
            bvR = doAct ? *(const float4*)(ab + HH + k0 + aCol) : make_float4(0.f, 0.f, 0.f, 0.f);
            aR0 = (grA0 < M) ? *(const float4*)(A + (long)grA0 * K + k0 + aCol)
                             : make_float4(0.f, 0.f, 0.f, 0.f);
            aR1 = (grA1 < M) ? *(const float4*)(A + (long)grA1 * K + k0 + aCol)
                             : make_float4(0.f, 0.f, 0.f, 0.f);
            bR0 = *(const float4*)(B + (long)(k0 + bRow) * Ncols + colBase + bCol);
            bR1 = *(const float4*)(B + (long)(k0 + bRow + 8) * Ncols + colBase + bCol);
        }
#pragma unroll
        for (int kk = 0; kk < 16; kk++) {
            const float* arow = &As[p][kk][ty * 8];
            const float* brow = &Bs[p][kk][tx * 8];
            u64 bq[4];
            u64 ad[8];
#pragma unroll
            for (int q = 0; q < 4; q++) {
                float2 af = *(const float2*)(arow + 2 * q);
                ad[2 * q]     = pack2(af.x, af.x);
                ad[2 * q + 1] = pack2(af.y, af.y);
                bq[q] = *(const u64*)(brow + 2 * q);
            }
#pragma unroll
            for (int i = 0; i < 8; i++)
#pragma unroll
                for (int jp = 0; jp < 4; jp++)
                    fma2(acc2[i][jp], ad[i], bq[jp], acc2[i][jp]);
        }
        if (more) {
            const int k0 = (kt + 1) << 4;
            const int q = p ^ 1;
#pragma unroll
            for (int s = 0; s < 2; s++) {
                float4 v = s ? aR1 : aR0;
                int gr = s ? grA1 : grA0;
                int r = aRow + s * 64;
                if (doAct && gr < M) {
                    v.x = fmaxf(fmaf(v.x, avR.x, bvR.x), 0.f);
                    v.y = fmaxf(fmaf(v.y, avR.y, bvR.y), 0.f);
                    v.z = fmaxf(fmaf(v.z, avR.z, bvR.z), 0.f);
                    v.w = fmaxf(fmaf(v.w, avR.w, bvR.w), 0.f);
                }
                if (doAcc && gr < M) {
                    float* ap = accOut + (long)gr * K + k0 + aCol;
                    float4 ac = *(const float4*)ap;
                    ac.x = fmaf(wres, v.x, ac.x);
                    ac.y = fmaf(wres, v.y, ac.y);
                    ac.z = fmaf(wres, v.z, ac.z);
                    ac.w = fmaf(wres, v.w, ac.w);
                    *(float4*)ap = ac;
                }
                As[q][aCol + 0][r] = v.x;
                As[q][aCol + 1][r] = v.y;
                As[q][aCol + 2][r] = v.z;
                As[q][aCol + 3][r] = v.w;
            }
            *(float4*)(&Bs[q][bRow][bCol]) = bR0;
            *(float4*)(&Bs[q][bRow + 8][bCol]) = bR1;
        }
        __syncthreads();
        p ^= 1;
    }

#pragma unroll
    for (int i = 0; i < 8; i++) {
        int gr = rowBase + ty * 8 + i;
        if (gr >= M) continue;
#pragma unroll
        for (int j = 0; j < 2; j++) {
            int gc = colBase + tx * 8 + j * 4;
            float4 bv = *(const float4*)(bias + gc);
            float2 p0 = unpack2(acc2[i][j * 2]);
            float2 p1 = unpack2(acc2[i][j * 2 + 1]);
            float o0 = p0.x + bv.x;
            float o1 = p0.y + bv.y;
            float o2 = p1.x + bv.z;
            float o3 = p1.y + bv.w;
            if (HALF_OUT) {
                __half2* hp = (__half2*)((__half*)Cout + (long)gr * Ncols + gc);
                hp[0] = __floats2half2_rn(o0, o1);
                hp[1] = __floats2half2_rn(o2, o3);
            } else {
                *(float4*)((float*)Cout + (long)gr * Ncols + gc) =
                    make_float4(o0, o1, o2, o3);
            }
        }
    }
}

// ---------------- gather SpMM (CSR, warp/node, fp16 src, fused BN stats) -----
__global__ __launch_bounds__(256) void spmm_kernel(
    const __half* __restrict__ t, const int* __restrict__ row,
    const int* __restrict__ src, const float* __restrict__ nrm,
    const float* __restrict__ selfn)
{
    __shared__ float sh[8][256];
    const int warp = threadIdx.x >> 5;
    const int lane = threadIdx.x & 31;
    const int node = blockIdx.x * 8 + warp;

    float racc[8];
#pragma unroll
    for (int j = 0; j < 8; j++) racc[j] = 0.f;

    const int beg = row[node];
    const int end = row[node + 1];
    int e = beg;
    for (; e + 1 < end; e += 2) {
        int s0 = src[e], s1 = src[e + 1];
        float n0 = nrm[e], n1 = nrm[e + 1];
        uint4 v0 = ((const uint4*)(t + (long)s0 * HH))[lane];
        uint4 v1 = ((const uint4*)(t + (long)s1 * HH))[lane];
        float2 f;
        f = h2f(v0.x); racc[0] = fmaf(f.x, n0, racc[0]); racc[1] = fmaf(f.y, n0, racc[1]);
        f = h2f(v0.y); racc[2] = fmaf(f.x, n0, racc[2]); racc[3] = fmaf(f.y, n0, racc[3]);
        f = h2f(v0.z); racc[4] = fmaf(f.x, n0, racc[4]); racc[5] = fmaf(f.y, n0, racc[5]);
        f = h2f(v0.w); racc[6] = fmaf(f.x, n0, racc[6]); racc[7] = fmaf(f.y, n0, racc[7]);
        f = h2f(v1.x); racc[0] = fmaf(f.x, n1, racc[0]); racc[1] = fmaf(f.y, n1, racc[1]);
        f = h2f(v1.y); racc[2] = fmaf(f.x, n1, racc[2]); racc[3] = fmaf(f.y, n1, racc[3]);
        f = h2f(v1.z); racc[4] = fmaf(f.x, n1, racc[4]); racc[5] = fmaf(f.y, n1, racc[5]);
        f = h2f(v1.w); racc[6] = fmaf(f.x, n1, racc[6]); racc[7] = fmaf(f.y, n1, racc[7]);
    }
    if (e < end) {
        int s0 = src[e];
        float n0 = nrm[e];
        uint4 v0 = ((const uint4*)(t + (long)s0 * HH))[lane];
        float2 f;
        f = h2f(v0.x); racc[0] = fmaf(f.x, n0, racc[0]); racc[1] = fmaf(f.y, n0, racc[1]);
        f = h2f(v0.y); racc[2] = fmaf(f.x, n0, racc[2]); racc[3] = fmaf(f.y, n0, racc[3]);
        f = h2f(v0.z); racc[4] = fmaf(f.x, n0, racc[4]); racc[5] = fmaf(f.y, n0, racc[5]);
        f = h2f(v0.w); racc[6] = fmaf(f.x, n0, racc[6]); racc[7] = fmaf(f.y, n0, racc[7]);
    }
    // self loop
    {
        float sf = selfn[node];
        uint4 v0 = ((const uint4*)(t + (long)node * HH))[lane];
        float2 f;
        f = h2f(v0.x); racc[0] = fmaf(f.x, sf, racc[0]); racc[1] = fmaf(f.y, sf, racc[1]);
        f = h2f(v0.y); racc[2] = fmaf(f.x, sf, racc[2]); racc[3] = fmaf(f.y, sf, racc[3]);
        f = h2f(v0.z); racc[4] = fmaf(f.x, sf, racc[4]); racc[5] = fmaf(f.y, sf, racc[5]);
        f = h2f(v0.w); racc[6] = fmaf(f.x, sf, racc[6]); racc[7] = fmaf(f.y, sf, racc[7]);
    }

    // write h (fp32) + stash row into smem for BN stats
    float4 w0 = make_float4(racc[0], racc[1], racc[2], racc[3]);
    float4 w1 = make_float4(racc[4], racc[5], racc[6], racc[7]);
    float4* dst = (float4*)(g_h + (long)node * HH + lane * 8);
    dst[0] = w0;
    dst[1] = w1;
    *(float4*)(&sh[warp][lane * 8]) = w0;
    *(float4*)(&sh[warp][lane * 8 + 4]) = w1;
    __syncthreads();

    // per-feature partial sums over the block's 8 nodes
    const int f = threadIdx.x;
    float s = 0.f, q = 0.f;
#pragma unroll
    for (int w = 0; w < 8; w++) {
        float v = sh[w][f];
        s += v;
        q = fmaf(v, v, q);
    }
    atomicAdd(&g_stats[f], s);
    atomicAdd(&g_stats[HH + f], q);
}

__global__ void bn_finalize_kernel(const float* __restrict__ gamma,
                                   const float* __restrict__ beta, int layer) {
    int f = threadIdx.x;
    float mu = g_stats[f] * (1.0f / NN);
    float var = g_stats[HH + f] * (1.0f / NN) - mu * mu;
    float rs = rsqrtf(var + EPSBN);
    float a = rs * gamma[layer * HH + f];
    float b = beta[layer * HH + f] - mu * a;
    g_ab[f] = a;
    g_ab[HH + f] = b;
}

// fused (layer-7 residual) + out FC + log-softmax: one block per node row
__global__ __launch_bounds__(128) void out_kernel(
    const float* __restrict__ outW, const float* __restrict__ outb,
    float* __restrict__ out)
{
    __shared__ float sacc[HH];
    __shared__ float sval[128];
    int r = blockIdx.x;
    int t = threadIdx.x;
    float w7 = g_w[LL - 1];
#pragma unroll
    for (int s = 0; s < 2; s++) {
        int f = t + s * 128;
        float hv = g_h[(long)r * HH + f];
        float act = fmaxf(fmaf(hv, g_ab[f], g_ab[HH + f]), 0.f);
        sacc[f] = fmaf(w7, act, g_acc[(long)r * HH + f]);
    }
    __syncthreads();
    float dot = 0.f;
    if (t < CC) {
        dot = outb[t];
#pragma unroll 8
        for (int k = 0; k < HH; k++)
            dot = fmaf(sacc[k], outW[k * CC + t], dot);
    }
    sval[t] = (t < CC) ? dot : -1e30f;
    __syncthreads();
    for (int s = 64; s > 0; s >>= 1) {
        if (t < s) sval[t] = fmaxf(sval[t], sval[t + s]);
        __syncthreads();
    }
    float mx = sval[0];
    __syncthreads();
    sval[t] = (t < CC) ? expf(dot - mx) : 0.f;
    __syncthreads();
    for (int s = 64; s > 0; s >>= 1) {
        if (t < s) sval[t] += sval[t + s];
        __syncthreads();
    }
    float lse = logf(sval[0]) + mx;
    if (t < CC) out[(long)r * CC + t] = dot - lse;
}

// ---------------- launch ------------------------------------------------------
extern "C" void kernel_launch(void* const* d_in, const int* in_sizes, int n_in,
                              void* d_out, int out_size) {
    const float* x     = (const float*)d_in[0];
    const int*   e1    = (const int*)d_in[1];
    const int*   e2    = (const int*)d_in[2];
    const float* inW   = (const float*)d_in[3];
    const float* inb   = (const float*)d_in[4];
    const float* convW = (const float*)d_in[5];
    const float* convB = (const float*)d_in[6];
    const float* gamma = (const float*)d_in[7];
    const float* beta  = (const float*)d_in[8];
    const float* outW  = (const float*)d_in[9];
    const float* outb  = (const float*)d_in[10];
    const float* lw    = (const float*)d_in[11];
    float* out = (float*)d_out;

    float *p_h, *p_acc, *p_stats, *p_s1, *p_s2, *p_n1, *p_n2, *p_ab, *p_w;
    __half* p_t;
    int *p_deg1, *p_deg2, *p_row1, *p_row2, *p_cur1, *p_cur2, *p_src1, *p_src2, *p_part;
    cudaGetSymbolAddress((void**)&p_h, g_h);
    cudaGetSymbolAddress((void**)&p_t, g_t);
    cudaGetSymbolAddress((void**)&p_acc, g_acc);
    cudaGetSymbolAddress((void**)&p_stats, g_stats);
    cudaGetSymbolAddress((void**)&p_ab, g_ab);
    cudaGetSymbolAddress((void**)&p_w, g_w);
    cudaGetSymbolAddress((void**)&p_s1, g_self1);
    cudaGetSymbolAddress((void**)&p_s2, g_self2);
    cudaGetSymbolAddress((void**)&p_n1, g_nrm1);
    cudaGetSymbolAddress((void**)&p_n2, g_nrm2);
    cudaGetSymbolAddress((void**)&p_deg1, g_deg1);
    cudaGetSymbolAddress((void**)&p_deg2, g_deg2);
    cudaGetSymbolAddress((void**)&p_row1, g_row1);
    cudaGetSymbolAddress((void**)&p_row2, g_row2);
    cudaGetSymbolAddress((void**)&p_cur1, g_cur1);
    cudaGetSymbolAddress((void**)&p_cur2, g_cur2);
    cudaGetSymbolAddress((void**)&p_src1, g_src1);
    cudaGetSymbolAddress((void**)&p_src2, g_src2);
    cudaGetSymbolAddress((void**)&p_part, g_part);

    const int Z = 256;
    // ---- adjacency prep: degrees, dinv, CSR build ----
    zero_kernel<<<(NN / 4 + Z - 1) / Z, Z>>>((float4*)p_deg1, NN / 4);
    zero_kernel<<<(NN / 4 + Z - 1) / Z, Z>>>((float4*)p_deg2, NN / 4);
    deg_kernel<<<(EE + Z - 1) / Z, Z>>>(e1, e2);
    dinv_kernel<<<(NN + Z - 1) / Z, Z>>>();
    scan1_kernel<<<NB_SCAN, 256>>>(p_deg1, p_row1, p_part);
    scan2_kernel<<<1, 256>>>(p_part);
    scan3_kernel<<<(NN + Z - 1) / Z, Z>>>(p_row1, p_part, p_cur1);
    scan1_kernel<<<NB_SCAN, 256>>>(p_deg2, p_row2, p_part);
    scan2_kernel<<<1, 256>>>(p_part);
    scan3_kernel<<<(NN + Z - 1) / Z, Z>>>(p_row2, p_part, p_cur2);
    fill_kernel<<<(EE + Z - 1) / Z, Z>>>(e1, e2);
    softmax_w_kernel<<<1, 32>>>(lw);

    const int NH4 = NN * HH / 4;
    zero_kernel<<<(NH4 + Z - 1) / Z, Z>>>((float4*)p_acc, NH4);

    // input FC: h = x @ in_W + in_b (fp32 out, no activation, no residual)
    dim3 gemmGrid(HH / 128, (NN + 127) / 128);
    sgemm_kernel<false><<<gemmGrid, 256>>>(x, inW, inb, p_h, NN, HH, FIN,
                                           nullptr, nullptr, 0, nullptr);

    for (int i = 0; i < LL; i++) {
        // t = act(h) @ convW[i] + convB[i]  (half out)
        // act = identity for i==0, else BN+ReLU of layer i-1.
        // For i>0, block x==0 also accumulates acc += w[i-1]*act(h) during A load.
        const float* abp = (i > 0) ? p_ab : nullptr;
        const float* wp  = (i > 0) ? p_w : nullptr;
        sgemm_kernel<true><<<gemmGrid, 256>>>(p_h, convW + (long)i * HH * HH,
                                              convB + (long)i * HH, p_t, NN, HH, HH,
                                              abp, wp, i - 1, p_acc);
        // h = A_hat_norm @ t via CSR gather (self loop + fused BN stats)
        zero_kernel<<<1, 128>>>((float4*)p_stats, 128);
        const int* rowp = (i < LL / 2) ? p_row1 : p_row2;
        const int* srcp = (i < LL / 2) ? p_src1 : p_src2;
        const float* nrmp = (i < LL / 2) ? p_n1 : p_n2;
        const float* selfp = (i < LL / 2) ? p_s1 : p_s2;
        spmm_kernel<<<NN / 8, 256>>>(p_t, rowp, srcp, nrmp, selfp);
        bn_finalize_kernel<<<1, 256>>>(gamma, beta, i);
    }

    // out FC (+ layer-7 weighted residual) + log_softmax
    out_kernel<<<NN, 128>>>(outW, outb, out);
}

// round 15
// speedup vs baseline: 1.0987x; 1.0987x over previous
#include <cuda_runtime.h>
#include <cuda_fp16.h>
#include <math.h>

#define NN 50000
#define EE 800000
#define FIN 128
#define HH 256
#define CC 112
#define LL 8
#define EPSBN 1e-5f
#define NB_SCAN 196   // ceil(NN/256)

typedef unsigned long long u64;

__device__ __forceinline__ u64 pack2(float lo, float hi) {
    u64 d; asm("mov.b64 %0, {%1, %2};" : "=l"(d) : "f"(lo), "f"(hi)); return d;
}
__device__ __forceinline__ void fma2(u64& d, u64 a, u64 b, u64 c) {
    asm("fma.rn.f32x2 %0, %1, %2, %3;" : "=l"(d) : "l"(a), "l"(b), "l"(c));
}
__device__ __forceinline__ float2 unpack2(u64 v) {
    float2 r; asm("mov.b64 {%0, %1}, %2;" : "=f"(r.x), "=f"(r.y) : "l"(v)); return r;
}
__device__ __forceinline__ float2 h2f(unsigned int u) {
    __half2 h = *reinterpret_cast<__half2*>(&u);
    return __half22float2(h);
}

// ---------------- scratch (device globals; no allocation allowed) ------------
__device__ __align__(16) float  g_h[NN * HH];
__device__ __align__(16) __half g_t[NN * HH];
__device__ __align__(16) float  g_acc[NN * HH];
__device__ __align__(16) int    g_deg1[NN];
__device__ __align__(16) int    g_deg2[NN];
__device__ __align__(16) int    g_row1[NN + 4];
__device__ __align__(16) int    g_row2[NN + 4];
__device__ __align__(16) int    g_cur1[NN];
__device__ __align__(16) int    g_cur2[NN];
__device__ __align__(16) int    g_src1[EE];
__device__ __align__(16) int    g_src2[EE];
__device__ __align__(16) float  g_nrm1[EE];
__device__ __align__(16) float  g_nrm2[EE];
__device__ __align__(16) float  g_dinv1[NN];
__device__ __align__(16) float  g_dinv2[NN];
__device__ __align__(16) float  g_self1[NN];
__device__ __align__(16) float  g_self2[NN];
__device__ __align__(16) int    g_part[256];
__device__ __align__(16) float  g_stats[2 * HH];   // sum, sumsq
__device__ __align__(16) float  g_ab[2 * HH];      // scale a, shift b
__device__ __align__(16) float  g_w[LL];

// ---------------- utility kernels -------------------------------------------
__global__ void zero_kernel(float4* p, int n4) {
    int i = blockIdx.x * blockDim.x + threadIdx.x;
    if (i < n4) p[i] = make_float4(0.f, 0.f, 0.f, 0.f);
}

__global__ void zero2_kernel(float4* p1, float4* p2, int n4) {
    int i = blockIdx.x * blockDim.x + threadIdx.x;
    if (i < n4) {
        p1[i] = make_float4(0.f, 0.f, 0.f, 0.f);
        p2[i] = make_float4(0.f, 0.f, 0.f, 0.f);
    }
}

__global__ void deg_kernel(const int* __restrict__ e1, const int* __restrict__ e2) {
    int i = blockIdx.x * blockDim.x + threadIdx.x;
    if (i < EE) {
        atomicAdd(&g_deg1[e1[EE + i]], 1);
        atomicAdd(&g_deg2[e2[EE + i]], 1);
    }
}

__global__ void dinv_kernel() {
    int i = blockIdx.x * blockDim.x + threadIdx.x;
    if (i < NN) {
        float d1 = rsqrtf((float)g_deg1[i] + 1.0f);   // +1 = self loop
        float d2 = rsqrtf((float)g_deg2[i] + 1.0f);
        g_dinv1[i] = d1;
        g_dinv2[i] = d2;
        g_self1[i] = d1 * d1;
        g_self2[i] = d2 * d2;
    }
}

__global__ void scan1_kernel(const int* __restrict__ deg, int* __restrict__ row,
                             int* __restrict__ partial) {
    __shared__ int s[256];
    int tid = threadIdx.x;
    int i = blockIdx.x * 256 + tid;
    int v = (i < NN) ? deg[i] : 0;
    s[tid] = v;
    __syncthreads();
#pragma unroll
    for (int off = 1; off < 256; off <<= 1) {
        int t = (tid >= off) ? s[tid - off] : 0;
        __syncthreads();
        s[tid] += t;
        __syncthreads();
    }
    if (i < NN) row[i] = s[tid] - v;   // exclusive
    if (tid == 255) partial[blockIdx.x] = s[255];
}

__global__ void scan2_kernel(int* __restrict__ partial) {
    __shared__ int s[256];
    int tid = threadIdx.x;
    int v = (tid < NB_SCAN) ? partial[tid] : 0;
    s[tid] = v;
    __syncthreads();
#pragma unroll
    for (int off = 1; off < 256; off <<= 1) {
        int t = (tid >= off) ? s[tid - off] : 0;
        __syncthreads();
        s[tid] += t;
        __syncthreads();
    }
    if (tid < NB_SCAN) partial[tid] = s[tid] - v;
}

__global__ void scan3_kernel(int* __restrict__ row, const int* __restrict__ partial,
                             int* __restrict__ cur) {
    int i = blockIdx.x * blockDim.x + threadIdx.x;
    if (i < NN) {
        int r = row[i] + partial[i >> 8];
        row[i] = r;
        cur[i] = r;
    }
    if (i == 0) row[NN] = EE;
}

__global__ void fill_kernel(const int* __restrict__ e1, const int* __restrict__ e2) {
    int i = blockIdx.x * blockDim.x + threadIdx.x;
    if (i < EE) {
        int s1 = e1[i], c1 = e1[EE + i];
        int p = atomicAdd(&g_cur1[c1], 1);
        g_src1[p] = s1;
        g_nrm1[p] = g_dinv1[s1] * g_dinv1[c1];
        int s2 = e2[i], c2 = e2[EE + i];
        p = atomicAdd(&g_cur2[c2], 1);
        g_src2[p] = s2;
        g_nrm2[p] = g_dinv2[s2] * g_dinv2[c2];
    }
}

__global__ void softmax_w_kernel(const float* __restrict__ lw) {
    if (threadIdx.x == 0 && blockIdx.x == 0) {
        float m = lw[0];
        for (int i = 1; i < LL; i++) m = fmaxf(m, lw[i]);
        float e[LL];
        float s = 0.f;
        for (int i = 0; i < LL; i++) { e[i] = expf(lw[i] - m); s += e[i]; }
        float inv = 1.0f / s;
        for (int i = 0; i < LL; i++) g_w[i] = e[i] * inv;
    }
}

// ---------------- SGEMM: C = act(A) @ B + bias (single-buffered, FMA2) -------
// act(v,k) = relu(ab[k]*v + ab[HH+k]) when ab != nullptr (fused BN+ReLU).
// When wPtr != nullptr and blockIdx.x == 0: accOut[r,k] += wPtr[widx]*act(A[r,k]).
// HALF_OUT: write C as __half, else float.
// 128x128 tile, BK=16, 256 threads, 8x8 per thread (8x4 f32x2 pairs).
template <bool HALF_OUT>
__global__ __launch_bounds__(256) void sgemm_kernel(
    const float* __restrict__ A, const float* __restrict__ B,
    const float* __restrict__ bias, void* __restrict__ Cout,
    int M, int Ncols, int K, const float* __restrict__ ab,
    const float* __restrict__ wPtr, int widx, float* __restrict__ accOut)
{
    __shared__ float As[16][128];
    __shared__ float Bs[16][128];
    const int tid = threadIdx.x;
    const int tx = tid & 15;
    const int ty = tid >> 4;
    const int rowBase = blockIdx.y * 128;
    const int colBase = blockIdx.x * 128;
    const int aRow = tid >> 2;          // 0..63
    const int aCol = (tid & 3) * 4;     // 0,4,8,12
    const int bRow = tid >> 5;          // 0..7
    const int bCol = (tid & 31) * 4;    // 0..124

    const bool doAct = (ab != nullptr);
    const bool doAcc = (wPtr != nullptr) && (blockIdx.x == 0);
    const float wres = doAcc ? wPtr[widx] : 0.f;

    u64 acc2[8][4];
#pragma unroll
    for (int i = 0; i < 8; i++)
#pragma unroll
        for (int j = 0; j < 4; j++) acc2[i][j] = 0ull;

    for (int k0 = 0; k0 < K; k0 += 16) {
        float4 av = make_float4(1.f, 1.f, 1.f, 1.f);
        float4 bv0 = make_float4(0.f, 0.f, 0.f, 0.f);
        if (doAct) {
            av = *(const float4*)(ab + k0 + aCol);
            bv0 = *(const float4*)(ab + HH + k0 + aCol);
        }
#pragma unroll
        for (int s = 0; s < 2; s++) {
            int r = aRow + s * 64;
            int gr = rowBase + r;
            float4 v = make_float4(0.f, 0.f, 0.f, 0.f);
            if (gr < M) {
                v = *(const float4*)(A + (long)gr * K + k0 + aCol);
                if (doAct) {
                    v.x = fmaxf(fmaf(v.x, av.x, bv0.x), 0.f);
                    v.y = fmaxf(fmaf(v.y, av.y, bv0.y), 0.f);
                    v.z = fmaxf(fmaf(v.z, av.z, bv0.z), 0.f);
                    v.w = fmaxf(fmaf(v.w, av.w, bv0.w), 0.f);
                }
                if (doAcc) {
                    float* ap = accOut + (long)gr * K + k0 + aCol;
                    float4 ac = *(const float4*)ap;
                    ac.x = fmaf(wres, v.x, ac.x);
                    ac.y = fmaf(wres, v.y, ac.y);
                    ac.z = fmaf(wres, v.z, ac.z);
                    ac.w = fmaf(wres, v.w, ac.w);
                    *(float4*)ap = ac;
                }
            }
            As[aCol + 0][r] = v.x;
            As[aCol + 1][r] = v.y;
            As[aCol + 2][r] = v.z;
            As[aCol + 3][r] = v.w;
        }
#pragma unroll
        for (int s = 0; s < 2; s++) {
            int r = bRow + s * 8;
            int gc = colBase + bCol;
            float4 v = make_float4(0.f, 0.f, 0.f, 0.f);
            if (gc + 3 < Ncols) {
                v = *(const float4*)(B + (long)(k0 + r) * Ncols + gc);
            }
            *(float4*)(&Bs[r][bCol]) = v;
        }
        __syncthreads();
#pragma unroll
        for (int kk = 0; kk < 16; kk++) {
            const float* arow = &As[kk][ty * 8];
            const float* brow = &Bs[kk][tx * 8];
            u64 bq[4];
            u64 ad[8];
#pragma unroll
            for (int q = 0; q < 4; q++) {
                float2 af = *(const float2*)(arow + 2 * q);
                ad[2 * q]     = pack2(af.x, af.x);
                ad[2 * q + 1] = pack2(af.y, af.y);
                bq[q] = *(const u64*)(brow + 2 * q);
            }
#pragma unroll
            for (int i = 0; i < 8; i++)
#pragma unroll
                for (int jp = 0; jp < 4; jp++)
                    fma2(acc2[i][jp], ad[i], bq[jp], acc2[i][jp]);
        }
        __syncthreads();
    }

#pragma unroll
    for (int i = 0; i < 8; i++) {
        int gr = rowBase + ty * 8 + i;
        if (gr >= M) continue;
#pragma unroll
        for (int j = 0; j < 2; j++) {
            int gc = colBase + tx * 8 + j * 4;
            if (gc + 3 < Ncols) {
                float4 bv = *(const float4*)(bias + gc);
                float2 p0 = unpack2(acc2[i][j * 2]);
                float2 p1 = unpack2(acc2[i][j * 2 + 1]);
                float o0 = p0.x + bv.x;
                float o1 = p0.y + bv.y;
                float o2 = p1.x + bv.z;
                float o3 = p1.y + bv.w;
                if (HALF_OUT) {
                    __half2* hp = (__half2*)((__half*)Cout + (long)gr * Ncols + gc);
                    hp[0] = __floats2half2_rn(o0, o1);
                    hp[1] = __floats2half2_rn(o2, o3);
                } else {
                    *(float4*)((float*)Cout + (long)gr * Ncols + gc) =
                        make_float4(o0, o1, o2, o3);
                }
            }
        }
    }
}

// ---- gather SpMM (CSR, warp/node, fp16 src, 4-edge unroll, fused BN stats) --
__device__ __forceinline__ void acc_edge(float* racc, uint4 v, float n) {
    float2 f;
    f = h2f(v.x); racc[0] = fmaf(f.x, n, racc[0]); racc[1] = fmaf(f.y, n, racc[1]);
    f = h2f(v.y); racc[2] = fmaf(f.x, n, racc[2]); racc[3] = fmaf(f.y, n, racc[3]);
    f = h2f(v.z); racc[4] = fmaf(f.x, n, racc[4]); racc[5] = fmaf(f.y, n, racc[5]);
    f = h2f(v.w); racc[6] = fmaf(f.x, n, racc[6]); racc[7] = fmaf(f.y, n, racc[7]);
}

__global__ __launch_bounds__(256) void spmm_kernel(
    const __half* __restrict__ t, const int* __restrict__ row,
    const int* __restrict__ src, const float* __restrict__ nrm,
    const float* __restrict__ selfn)
{
    __shared__ float sh[8][256];
    const int warp = threadIdx.x >> 5;
    const int lane = threadIdx.x & 31;
    const int node = blockIdx.x * 8 + warp;

    float racc[8];
#pragma unroll
    for (int j = 0; j < 8; j++) racc[j] = 0.f;

    const int beg = row[node];
    const int end = row[node + 1];
    int e = beg;
    for (; e + 3 < end; e += 4) {
        int s0 = src[e], s1 = src[e + 1], s2 = src[e + 2], s3 = src[e + 3];
        float n0 = nrm[e], n1 = nrm[e + 1], n2 = nrm[e + 2], n3 = nrm[e + 3];
        uint4 v0 = ((const uint4*)(t + (long)s0 * HH))[lane];
        uint4 v1 = ((const uint4*)(t + (long)s1 * HH))[lane];
        uint4 v2 = ((const uint4*)(t + (long)s2 * HH))[lane];
        uint4 v3 = ((const uint4*)(t + (long)s3 * HH))[lane];
        acc_edge(racc, v0, n0);
        acc_edge(racc, v1, n1);
        acc_edge(racc, v2, n2);
        acc_edge(racc, v3, n3);
    }
    for (; e < end; e++) {
        int s0 = src[e];
        float n0 = nrm[e];
        uint4 v0 = ((const uint4*)(t + (long)s0 * HH))[lane];
        acc_edge(racc, v0, n0);
    }
    // self loop
    {
        float sf = selfn[node];
        uint4 v0 = ((const uint4*)(t + (long)node * HH))[lane];
        acc_edge(racc, v0, sf);
    }

    // write h (fp32) + stash row into smem for BN stats
    float4 w0 = make_float4(racc[0], racc[1], racc[2], racc[3]);
    float4 w1 = make_float4(racc[4], racc[5], racc[6], racc[7]);
    float4* dst = (float4*)(g_h + (long)node * HH + lane * 8);
    dst[0] = w0;
    dst[1] = w1;
    *(float4*)(&sh[warp][lane * 8]) = w0;
    *(float4*)(&sh[warp][lane * 8 + 4]) = w1;
    __syncthreads();

    // per-feature partial sums over the block's 8 nodes
    const int f = threadIdx.x;
    float s = 0.f, q = 0.f;
#pragma unroll
    for (int w = 0; w < 8; w++) {
        float v = sh[w][f];
        s += v;
        q = fmaf(v, v, q);
    }
    atomicAdd(&g_stats[f], s);
    atomicAdd(&g_stats[HH + f], q);
}

// finalizes BN coefficients AND clears stats for the next layer
__global__ void bn_finalize_kernel(const float* __restrict__ gamma,
                                   const float* __restrict__ beta, int layer) {
    int f = threadIdx.x;
    float mu = g_stats[f] * (1.0f / NN);
    float var = g_stats[HH + f] * (1.0f / NN) - mu * mu;
    float rs = rsqrtf(var + EPSBN);
    float a = rs * gamma[layer * HH + f];
    float b = beta[layer * HH + f] - mu * a;
    g_ab[f] = a;
    g_ab[HH + f] = b;
    g_stats[f] = 0.f;
    g_stats[HH + f] = 0.f;
}

// fused (layer-7 residual) + out FC + log-softmax: one block per node row
__global__ __launch_bounds__(128) void out_kernel(
    const float* __restrict__ outW, const float* __restrict__ outb,
    float* __restrict__ out)
{
    __shared__ float sacc[HH];
    __shared__ float sval[128];
    int r = blockIdx.x;
    int t = threadIdx.x;
    float w7 = g_w[LL - 1];
#pragma unroll
    for (int s = 0; s < 2; s++) {
        int f = t + s * 128;
        float hv = g_h[(long)r * HH + f];
        float act = fmaxf(fmaf(hv, g_ab[f], g_ab[HH + f]), 0.f);
        sacc[f] = fmaf(w7, act, g_acc[(long)r * HH + f]);
    }
    __syncthreads();
    float dot = 0.f;
    if (t < CC) {
        dot = outb[t];
#pragma unroll 8
        for (int k = 0; k < HH; k++)
            dot = fmaf(sacc[k], outW[k * CC + t], dot);
    }
    sval[t] = (t < CC) ? dot : -1e30f;
    __syncthreads();
    for (int s = 64; s > 0; s >>= 1) {
        if (t < s) sval[t] = fmaxf(sval[t], sval[t + s]);
        __syncthreads();
    }
    float mx = sval[0];
    __syncthreads();
    sval[t] = (t < CC) ? expf(dot - mx) : 0.f;
    __syncthreads();
    for (int s = 64; s > 0; s >>= 1) {
        if (t < s) sval[t] += sval[t + s];
        __syncthreads();
    }
    float lse = logf(sval[0]) + mx;
    if (t < CC) out[(long)r * CC + t] = dot - lse;
}

// ---------------- launch ------------------------------------------------------
extern "C" void kernel_launch(void* const* d_in, const int* in_sizes, int n_in,
                              void* d_out, int out_size) {
    const float* x     = (const float*)d_in[0];
    const int*   e1    = (const int*)d_in[1];
    const int*   e2    = (const int*)d_in[2];
    const float* inW   = (const float*)d_in[3];
    const float* inb   = (const float*)d_in[4];
    const float* convW = (const float*)d_in[5];
    const float* convB = (const float*)d_in[6];
    const float* gamma = (const float*)d_in[7];
    const float* beta  = (const float*)d_in[8];
    const float* outW  = (const float*)d_in[9];
    const float* outb  = (const float*)d_in[10];
    const float* lw    = (const float*)d_in[11];
    float* out = (float*)d_out;

    float *p_h, *p_acc, *p_stats, *p_s1, *p_s2, *p_n1, *p_n2, *p_ab, *p_w;
    __half* p_t;
    int *p_deg1, *p_deg2, *p_row1, *p_row2, *p_cur1, *p_cur2, *p_src1, *p_src2, *p_part;
    cudaGetSymbolAddress((void**)&p_h, g_h);
    cudaGetSymbolAddress((void**)&p_t, g_t);
    cudaGetSymbolAddress((void**)&p_acc, g_acc);
    cudaGetSymbolAddress((void**)&p_stats, g_stats);
    cudaGetSymbolAddress((void**)&p_ab, g_ab);
    cudaGetSymbolAddress((void**)&p_w, g_w);
    cudaGetSymbolAddress((void**)&p_s1, g_self1);
    cudaGetSymbolAddress((void**)&p_s2, g_self2);
    cudaGetSymbolAddress((void**)&p_n1, g_nrm1);
    cudaGetSymbolAddress((void**)&p_n2, g_nrm2);
    cudaGetSymbolAddress((void**)&p_deg1, g_deg1);
    cudaGetSymbolAddress((void**)&p_deg2, g_deg2);
    cudaGetSymbolAddress((void**)&p_row1, g_row1);
    cudaGetSymbolAddress((void**)&p_row2, g_row2);
    cudaGetSymbolAddress((void**)&p_cur1, g_cur1);
    cudaGetSymbolAddress((void**)&p_cur2, g_cur2);
    cudaGetSymbolAddress((void**)&p_src1, g_src1);
    cudaGetSymbolAddress((void**)&p_src2, g_src2);
    cudaGetSymbolAddress((void**)&p_part, g_part);

    const int Z = 256;
    const int NH4 = NN * HH / 4;
    dim3 gemmGrid(HH / 128, (NN + 127) / 128);

    // Launches 1-5: prep the input GEMM (launch 6) does NOT depend on is
    // front-loaded so ncu (-s 5 -c 1) profiles the input GEMM.
    zero2_kernel<<<(NN / 4 + Z - 1) / Z, Z>>>((float4*)p_deg1, (float4*)p_deg2, NN / 4); // 1
    deg_kernel<<<(EE + Z - 1) / Z, Z>>>(e1, e2);                                          // 2
    dinv_kernel<<<(NN + Z - 1) / Z, Z>>>();                                               // 3
    zero_kernel<<<(NH4 + Z - 1) / Z, Z>>>((float4*)p_acc, NH4);                           // 4
    softmax_w_kernel<<<1, 32>>>(lw);                                                      // 5

    // input FC: h = x @ in_W + in_b (launch 6 — profiled)
    sgemm_kernel<false><<<gemmGrid, 256>>>(x, inW, inb, p_h, NN, HH, FIN,
                                           nullptr, nullptr, 0, nullptr);

    // remaining adjacency prep (needed before first spmm)
    zero_kernel<<<1, 128>>>((float4*)p_stats, 128);
    scan1_kernel<<<NB_SCAN, 256>>>(p_deg1, p_row1, p_part);
    scan2_kernel<<<1, 256>>>(p_part);
    scan3_kernel<<<(NN + Z - 1) / Z, Z>>>(p_row1, p_part, p_cur1);
    scan1_kernel<<<NB_SCAN, 256>>>(p_deg2, p_row2, p_part);
    scan2_kernel<<<1, 256>>>(p_part);
    scan3_kernel<<<(NN + Z - 1) / Z, Z>>>(p_row2, p_part, p_cur2);
    fill_kernel<<<(EE + Z - 1) / Z, Z>>>(e1, e2);

    for (int i = 0; i < LL; i++) {
        // t = act(h) @ convW[i] + convB[i]  (half out)
        // act = identity for i==0, else BN+ReLU of layer i-1.
        // For i>0, block x==0 also accumulates acc += w[i-1]*act(h) during A load.
        const float* abp = (i > 0) ? p_ab : nullptr;
        const float* wp  = (i > 0) ? p_w : nullptr;
        sgemm_kernel<true><<<gemmGrid, 256>>>(p_h, convW + (long)i * HH * HH,
                                              convB + (long)i * HH, p_t, NN, HH, HH,
                                              abp, wp, i - 1, p_acc);
        // h = A_hat_norm @ t via CSR gather (self loop + fused BN stats)
        const int* rowp = (i < LL / 2) ? p_row1 : p_row2;
        const int* srcp = (i < LL / 2) ? p_src1 : p_src2;
        const float* nrmp = (i < LL / 2) ? p_n1 : p_n2;
        const float* selfp = (i < LL / 2) ? p_s1 : p_s2;
        spmm_kernel<<<NN / 8, 256>>>(p_t, rowp, srcp, nrmp, selfp);
        // BN coefficients (also clears stats for next layer)
        bn_finalize_kernel<<<1, 256>>>(gamma, beta, i);
    }

    // out FC (+ layer-7 weighted residual) + log_softmax
    out_kernel<<<NN, 128>>>(outW, outb, out);
}